// round 1
// baseline (speedup 1.0000x reference)
#include <cuda_runtime.h>
#include <math.h>

// ---------------- problem constants ----------------
#define BATCH 16
#define SEQ   1024
#define HID   512
#define HEADS 8
#define DH    64
#define PF    2048
#define MTOT  (BATCH * SEQ)     // 16384 rows

// ---------------- scratch (static device memory; no runtime alloc) ----------
__device__ float g_q  [MTOT * HID];
__device__ float g_k  [MTOT * HID];
__device__ float g_v  [MTOT * HID];
__device__ float g_ctx[MTOT * HID];
__device__ float g_xs [MTOT * HID];   // residual sums
__device__ float g_xn [MTOT * HID];   // post-LN 1
__device__ float g_x2 [MTOT * HID];   // post-LN 2
__device__ float g_h  [MTOT * PF];    // FFN hidden
__device__ float g_pool[BATCH * HID];

// ================= GEMM: C[M,N] = A[M,K] @ B[N,K]^T + bias (+res) (+relu) ===
// A row-major [M,K]; B row-major [N,K] (torch-style weight). 128x128x16 tile,
// 256 threads, 8x8 per-thread register tile. M%128==0, N%128==0, K%16==0 for
// every call in this problem, so no bounds checks.
#define BM 128
#define BN 128
#define BKK 16

__global__ __launch_bounds__(256)
void gemm_bias_kernel(const float* __restrict__ A, const float* __restrict__ B,
                      const float* __restrict__ bias, const float* __restrict__ res,
                      float* __restrict__ C, int M, int N, int K, int relu)
{
    __shared__ float As[BKK][BM + 4];
    __shared__ float Bs[BKK][BN + 4];

    const int tid = threadIdx.x;
    const int m0 = blockIdx.y * BM;
    const int n0 = blockIdx.x * BN;
    const int ry = tid >> 4;   // 0..15 -> rows ry*8..ry*8+7
    const int cx = tid & 15;   // 0..15 -> cols cx*8..cx*8+7

    float acc[8][8];
#pragma unroll
    for (int i = 0; i < 8; i++)
#pragma unroll
        for (int j = 0; j < 8; j++) acc[i][j] = 0.f;

    for (int k0 = 0; k0 < K; k0 += BKK) {
        // load + transpose 128x16 tiles of A and B into shared
#pragma unroll
        for (int it = 0; it < 2; it++) {
            int vec = tid + it * 256;          // 0..511
            int row = vec >> 2;                // 0..127
            int c4  = (vec & 3) * 4;           // 0,4,8,12
            float4 va = *(const float4*)&A[(m0 + row) * K + k0 + c4];
            As[c4 + 0][row] = va.x; As[c4 + 1][row] = va.y;
            As[c4 + 2][row] = va.z; As[c4 + 3][row] = va.w;
            float4 vb = *(const float4*)&B[(n0 + row) * K + k0 + c4];
            Bs[c4 + 0][row] = vb.x; Bs[c4 + 1][row] = vb.y;
            Bs[c4 + 2][row] = vb.z; Bs[c4 + 3][row] = vb.w;
        }
        __syncthreads();

#pragma unroll
        for (int kk = 0; kk < BKK; kk++) {
            float a[8], b[8];
            *(float4*)&a[0] = *(const float4*)&As[kk][ry * 8];
            *(float4*)&a[4] = *(const float4*)&As[kk][ry * 8 + 4];
            *(float4*)&b[0] = *(const float4*)&Bs[kk][cx * 8];
            *(float4*)&b[4] = *(const float4*)&Bs[kk][cx * 8 + 4];
#pragma unroll
            for (int i = 0; i < 8; i++)
#pragma unroll
                for (int j = 0; j < 8; j++)
                    acc[i][j] = fmaf(a[i], b[j], acc[i][j]);
        }
        __syncthreads();
    }

#pragma unroll
    for (int i = 0; i < 8; i++) {
        int m = m0 + ry * 8 + i;
#pragma unroll
        for (int j = 0; j < 8; j++) {
            int n = n0 + cx * 8 + j;
            float vv = acc[i][j] + bias[n];
            if (res) vv += res[m * N + n];
            if (relu) vv = fmaxf(vv, 0.f);
            C[m * N + n] = vv;
        }
    }
}

// ================= flash-style attention =====================================
// One block: (q-tile of 64, head, batch). 256 threads. Tiles of 64 keys.
// Online softmax; everything in SMEM; no O(T^2) HBM traffic.
#define ATTN_SMEM ((4 * 64 * 65 + 3 * 64) * 4)

__global__ __launch_bounds__(256)
void attn_kernel(const float* __restrict__ Q, const float* __restrict__ K,
                 const float* __restrict__ V, float* __restrict__ O)
{
    extern __shared__ float sm[];
    float* Qs = sm;                 // 64 x 65
    float* Ks = Qs + 64 * 65;
    float* Vs = Ks + 64 * 65;
    float* Ss = Vs + 64 * 65;
    float* mrow = Ss + 64 * 65;     // 64
    float* lrow = mrow + 64;
    float* arow = lrow + 64;

    const int tid = threadIdx.x;
    const int qt = blockIdx.x, h = blockIdx.y, b = blockIdx.z;
    const int q0 = qt * 64;

    // load Q tile (pre-scaled by 1/sqrt(dh) = 0.125)
    for (int idx = tid; idx < 4096; idx += 256) {
        int q = idx >> 6, d = idx & 63;
        Qs[q * 65 + d] = Q[((b * SEQ + q0 + q) * HEADS + h) * DH + d] * 0.125f;
    }
    if (tid < 64) { mrow[tid] = -1e30f; lrow[tid] = 0.f; }

    const int ty = tid >> 4, tx = tid & 15;
    float o[4][4] = {};

    for (int kt = 0; kt < SEQ / 64; kt++) {
        __syncthreads();   // protects Ks/Vs reuse + first-iter Q/m/l init
        int k0 = kt * 64;
        for (int idx = tid; idx < 4096; idx += 256) {
            int r = idx >> 6, d = idx & 63;
            int g = ((b * SEQ + k0 + r) * HEADS + h) * DH + d;
            Ks[r * 65 + d] = K[g];
            Vs[r * 65 + d] = V[g];
        }
        __syncthreads();

        // S = Q @ K^T  (each thread 4x4)
        float s[4][4] = {};
#pragma unroll
        for (int d = 0; d < 64; d++) {
            float a[4], bb[4];
#pragma unroll
            for (int i = 0; i < 4; i++) a[i]  = Qs[(ty * 4 + i) * 65 + d];
#pragma unroll
            for (int j = 0; j < 4; j++) bb[j] = Ks[(tx * 4 + j) * 65 + d];
#pragma unroll
            for (int i = 0; i < 4; i++)
#pragma unroll
                for (int j = 0; j < 4; j++)
                    s[i][j] = fmaf(a[i], bb[j], s[i][j]);
        }
#pragma unroll
        for (int i = 0; i < 4; i++)
#pragma unroll
            for (int j = 0; j < 4; j++)
                Ss[(ty * 4 + i) * 65 + tx * 4 + j] = s[i][j];
        __syncthreads();

        // online softmax row update (one thread per q-row)
        if (tid < 64) {
            float mold = mrow[tid];
            float mx = mold;
#pragma unroll 8
            for (int kk = 0; kk < 64; kk++) mx = fmaxf(mx, Ss[tid * 65 + kk]);
            float alpha = __expf(mold - mx);
            float l = lrow[tid] * alpha;
#pragma unroll 8
            for (int kk = 0; kk < 64; kk++) {
                float p = __expf(Ss[tid * 65 + kk] - mx);
                Ss[tid * 65 + kk] = p;
                l += p;
            }
            mrow[tid] = mx; lrow[tid] = l; arow[tid] = alpha;
        }
        __syncthreads();

        // rescale accumulators, then O += P @ V
#pragma unroll
        for (int i = 0; i < 4; i++) {
            float al = arow[ty * 4 + i];
#pragma unroll
            for (int j = 0; j < 4; j++) o[i][j] *= al;
        }
#pragma unroll
        for (int kk = 0; kk < 64; kk++) {
            float a[4], bb[4];
#pragma unroll
            for (int i = 0; i < 4; i++) a[i]  = Ss[(ty * 4 + i) * 65 + kk];
#pragma unroll
            for (int j = 0; j < 4; j++) bb[j] = Vs[kk * 65 + tx * 4 + j];
#pragma unroll
            for (int i = 0; i < 4; i++)
#pragma unroll
                for (int j = 0; j < 4; j++)
                    o[i][j] = fmaf(a[i], bb[j], o[i][j]);
        }
    }

#pragma unroll
    for (int i = 0; i < 4; i++) {
        float inv = 1.f / lrow[ty * 4 + i];
#pragma unroll
        for (int j = 0; j < 4; j++)
            O[((b * SEQ + q0 + ty * 4 + i) * HEADS + h) * DH + tx * 4 + j] = o[i][j] * inv;
    }
}

// ================= LayerNorm (one block per row of 512) ======================
__global__ __launch_bounds__(128)
void ln_kernel(const float* __restrict__ in, const float* __restrict__ gam,
               const float* __restrict__ bet, float* __restrict__ out)
{
    const int row = blockIdx.x;
    const int tid = threadIdx.x;
    const float* p = in + row * HID;

    float4 v = *(const float4*)&p[tid * 4];
    float s  = v.x + v.y + v.z + v.w;
    float ss = v.x * v.x + v.y * v.y + v.z * v.z + v.w * v.w;
#pragma unroll
    for (int off = 16; off; off >>= 1) {
        s  += __shfl_down_sync(0xffffffffu, s,  off);
        ss += __shfl_down_sync(0xffffffffu, ss, off);
    }
    __shared__ float sh_s[4], sh_ss[4];
    if ((tid & 31) == 0) { sh_s[tid >> 5] = s; sh_ss[tid >> 5] = ss; }
    __syncthreads();
    float tot  = sh_s[0]  + sh_s[1]  + sh_s[2]  + sh_s[3];
    float tot2 = sh_ss[0] + sh_ss[1] + sh_ss[2] + sh_ss[3];
    float mean = tot * (1.f / HID);
    float var  = tot2 * (1.f / HID) - mean * mean;
    float rstd = rsqrtf(var + 1e-5f);

    float4 gg = *(const float4*)&gam[tid * 4];
    float4 bb = *(const float4*)&bet[tid * 4];
    float4 r;
    r.x = (v.x - mean) * rstd * gg.x + bb.x;
    r.y = (v.y - mean) * rstd * gg.y + bb.y;
    r.z = (v.z - mean) * rstd * gg.z + bb.z;
    r.w = (v.w - mean) * rstd * gg.w + bb.w;
    *(float4*)&out[row * HID + tid * 4] = r;
}

// ================= norm-softmax pooling (one block per batch) ================
__global__ __launch_bounds__(512)
void pool_kernel(const float* __restrict__ x, float* __restrict__ pooled)
{
    __shared__ float sn[SEQ];
    __shared__ float red[512];
    const int b = blockIdx.x, tid = threadIdx.x;
    const float* xb = x + b * SEQ * HID;

    for (int t = tid; t < SEQ; t += 512) {
        const float* r = xb + t * HID;
        float ss = 0.f;
        for (int d = 0; d < HID; d += 4) {
            float4 v = *(const float4*)&r[d];
            ss += v.x * v.x + v.y * v.y + v.z * v.z + v.w * v.w;
        }
        sn[t] = sqrtf(ss);
    }
    __syncthreads();

    red[tid] = fmaxf(sn[tid], sn[tid + 512]);
    __syncthreads();
    for (int off = 256; off; off >>= 1) {
        if (tid < off) red[tid] = fmaxf(red[tid], red[tid + off]);
        __syncthreads();
    }
    float mx = red[0];
    __syncthreads();

    float e0 = __expf(sn[tid] - mx);
    float e1 = __expf(sn[tid + 512] - mx);
    sn[tid] = e0; sn[tid + 512] = e1;
    red[tid] = e0 + e1;
    __syncthreads();
    for (int off = 256; off; off >>= 1) {
        if (tid < off) red[tid] += red[tid + off];
        __syncthreads();
    }
    float inv = 1.f / red[0];

    float acc = 0.f;
    for (int t = 0; t < SEQ; t++)
        acc = fmaf(sn[t], xb[t * HID + tid], acc);
    pooled[b * HID + tid] = acc * inv;
}

// ================= classifier head (one block per batch) =====================
__global__ __launch_bounds__(256)
void cls_kernel(const float* __restrict__ pooled,
                const float* __restrict__ w1, const float* __restrict__ b1,
                const float* __restrict__ w2, const float* __restrict__ b2,
                float* __restrict__ out)
{
    __shared__ float ps[HID];
    __shared__ float hs[256];
    const int b = blockIdx.x, tid = threadIdx.x;
    ps[tid]       = pooled[b * HID + tid];
    ps[tid + 256] = pooled[b * HID + tid + 256];
    __syncthreads();

    float acc = b1[tid];
    const float* wr = w1 + tid * HID;
    for (int k2 = 0; k2 < HID; k2 += 4) {
        float4 w = *(const float4*)&wr[k2];
        acc += w.x * ps[k2] + w.y * ps[k2 + 1] + w.z * ps[k2 + 2] + w.w * ps[k2 + 3];
    }
    hs[tid] = fmaxf(acc, 0.f);
    __syncthreads();

    if (tid < 2) {
        float a = b2[tid];
        const float* w = w2 + tid * 256;
        for (int j = 0; j < 256; j++) a = fmaf(hs[j], w[j], a);
        out[b * 2 + tid] = a;
    }
}

// ================= launch ====================================================
extern "C" void kernel_launch(void* const* d_in, const int* in_sizes, int n_in,
                              void* d_out, int out_size)
{
    const float* trg   = (const float*)d_in[0];
    const float* src   = (const float*)d_in[1];
    const float* ln_g  = (const float*)d_in[2];
    const float* ln_b  = (const float*)d_in[3];
    const float* wq    = (const float*)d_in[4];
    const float* bq    = (const float*)d_in[5];
    const float* wk    = (const float*)d_in[6];
    const float* bk    = (const float*)d_in[7];
    const float* wv    = (const float*)d_in[8];
    const float* bv    = (const float*)d_in[9];
    const float* wo    = (const float*)d_in[10];
    const float* bo    = (const float*)d_in[11];
    const float* pf1_w = (const float*)d_in[12];
    const float* pf1_b = (const float*)d_in[13];
    const float* pf2_w = (const float*)d_in[14];
    const float* pf2_b = (const float*)d_in[15];
    const float* fc1_w = (const float*)d_in[16];
    const float* fc1_b = (const float*)d_in[17];
    const float* fc2_w = (const float*)d_in[18];
    const float* fc2_b = (const float*)d_in[19];
    float* out = (float*)d_out;

    float *q, *k, *v, *ctx, *xs, *xn, *x2, *hb, *pool;
    cudaGetSymbolAddress((void**)&q,    g_q);
    cudaGetSymbolAddress((void**)&k,    g_k);
    cudaGetSymbolAddress((void**)&v,    g_v);
    cudaGetSymbolAddress((void**)&ctx,  g_ctx);
    cudaGetSymbolAddress((void**)&xs,   g_xs);
    cudaGetSymbolAddress((void**)&xn,   g_xn);
    cudaGetSymbolAddress((void**)&x2,   g_x2);
    cudaGetSymbolAddress((void**)&hb,   g_h);
    cudaGetSymbolAddress((void**)&pool, g_pool);

    cudaFuncSetAttribute(attn_kernel,
                         cudaFuncAttributeMaxDynamicSharedMemorySize, ATTN_SMEM);

    const int M = MTOT;
    dim3 thr(256);
    dim3 g512(HID / BN, M / BM);     // (4, 128)
    dim3 gpf (PF  / BN, M / BM);     // (16, 128)

    // projections
    gemm_bias_kernel<<<g512, thr>>>(trg, wq, bq, nullptr, q, M, HID, HID, 0);
    gemm_bias_kernel<<<g512, thr>>>(src, wk, bk, nullptr, k, M, HID, HID, 0);
    gemm_bias_kernel<<<g512, thr>>>(src, wv, bv, nullptr, v, M, HID, HID, 0);

    // attention
    attn_kernel<<<dim3(SEQ / 64, HEADS, BATCH), 256, ATTN_SMEM>>>(q, k, v, ctx);

    // O-projection + residual, LN
    gemm_bias_kernel<<<g512, thr>>>(ctx, wo, bo, trg, xs, M, HID, HID, 0);
    ln_kernel<<<M, 128>>>(xs, ln_g, ln_b, xn);

    // FFN + residual, LN
    gemm_bias_kernel<<<gpf,  thr>>>(xn, pf1_w, pf1_b, nullptr, hb, M, PF, HID, 1);
    gemm_bias_kernel<<<g512, thr>>>(hb, pf2_w, pf2_b, xn, xs, M, HID, PF, 0);
    ln_kernel<<<M, 128>>>(xs, ln_g, ln_b, x2);

    // pooling + classifier
    pool_kernel<<<BATCH, 512>>>(x2, pool);
    cls_kernel<<<BATCH, 256>>>(pool, fc1_w, fc1_b, fc2_w, fc2_b, out);
}

// round 4
// speedup vs baseline: 1.1392x; 1.1392x over previous
#include <cuda_runtime.h>
#include <math.h>
#include <stdint.h>

// ---------------- problem constants ----------------
#define BATCH 16
#define SEQ   1024
#define HID   512
#define HEADS 8
#define DH    64
#define PF    2048
#define MTOT  (BATCH * SEQ)     // 16384 rows

// ---------------- scratch (static device memory; no runtime alloc) ----------
__device__ float g_q  [MTOT * HID];
__device__ float g_k  [MTOT * HID];
__device__ float g_v  [MTOT * HID];
__device__ float g_ctx[MTOT * HID];
__device__ float g_xs [MTOT * HID];
__device__ float g_xn [MTOT * HID];
__device__ float g_x2 [MTOT * HID];
__device__ float g_h  [MTOT * PF];
__device__ float g_pool[BATCH * HID];

// ================= 3xTF32 tensor-core GEMM ===================================
// C[M,N] = A[M,K] @ B[N,K]^T + bias (+res) (+relu)
// 128x128x32 block tile, 256 threads (8 warps), 32x64 warp tile,
// mma.sync.aligned.m16n8k8 tf32 with hi/lo error compensation (3 mmas):
//   acc += lo(A)*hi(B) + hi(A)*lo(B) + hi(A)*hi(B)   (lo*lo dropped, ~2^-22)

__device__ __forceinline__ void cp16(float* dst, const float* src) {
    uint32_t s = (uint32_t)__cvta_generic_to_shared(dst);
    asm volatile("cp.async.cg.shared.global [%0], [%1], 16;\n" :: "r"(s), "l"(src));
}
__device__ __forceinline__ uint32_t f2tf32(float x) {
    uint32_t u;
    asm("cvt.rna.tf32.f32 %0, %1;" : "=r"(u) : "f"(x));
    return u;
}
__device__ __forceinline__ void split_tf32(float x, uint32_t& hi, uint32_t& lo) {
    hi = f2tf32(x);
    lo = f2tf32(x - __uint_as_float(hi));
}
// smem float index for logical (row m, col k) within a 128x32 tile,
// 128B-row XOR swizzle on 16B chunks.
__device__ __forceinline__ int sw(int m, int k) {
    return m * 32 + ((((k >> 2) ^ (m & 7)) << 2) | (k & 3));
}

#define MMA_TF32(c, a0, a1, a2, a3, b0, b1)                                   \
    asm volatile(                                                             \
        "mma.sync.aligned.m16n8k8.row.col.f32.tf32.tf32.f32 "                 \
        "{%0,%1,%2,%3},{%4,%5,%6,%7},{%8,%9},{%0,%1,%2,%3};"                  \
        : "+f"(c[0]), "+f"(c[1]), "+f"(c[2]), "+f"(c[3])                      \
        : "r"(a0), "r"(a1), "r"(a2), "r"(a3), "r"(b0), "r"(b1))

__global__ __launch_bounds__(256)
void gemm_tf32x3_kernel(const float* __restrict__ A, const float* __restrict__ B,
                        const float* __restrict__ bias, const float* __restrict__ res,
                        float* __restrict__ C, int M, int N, int K, int relu)
{
    extern __shared__ float gsm[];   // [2 bufs][A 4096 | B 4096] floats = 64KB

    const int tid  = threadIdx.x;
    const int warp = tid >> 5, lane = tid & 31;
    const int gid  = lane >> 2, tq = lane & 3;
    const int m0   = blockIdx.y * 128, n0 = blockIdx.x * 128;
    const int wm0  = (warp >> 1) * 32, wn0 = (warp & 1) * 64;

    float acc[2][8][4];
#pragma unroll
    for (int mi = 0; mi < 2; mi++)
#pragma unroll
        for (int nj = 0; nj < 8; nj++)
#pragma unroll
            for (int r = 0; r < 4; r++) acc[mi][nj][r] = 0.f;

    const float* Abase = A + (size_t)m0 * K;
    const float* Bbase = B + (size_t)n0 * K;
    const int T = K >> 5;   // K/32 tiles

    // ---- prefetch tile 0 ----
    {
        float* sA = gsm;
        float* sB = gsm + 4096;
#pragma unroll
        for (int i = 0; i < 4; i++) {
            int v = tid + i * 256;         // 0..1023 chunk index
            int r = v >> 3, c = v & 7;
            int d = r * 32 + ((c ^ (r & 7)) << 2);
            cp16(sA + d, Abase + (size_t)r * K + c * 4);
            cp16(sB + d, Bbase + (size_t)r * K + c * 4);
        }
        asm volatile("cp.async.commit_group;\n" ::: "memory");
    }

    for (int t = 0; t < T; t++) {
        if (t + 1 < T) {
            int k0 = (t + 1) << 5;
            float* sA = gsm + ((t + 1) & 1) * 8192;
            float* sB = sA + 4096;
#pragma unroll
            for (int i = 0; i < 4; i++) {
                int v = tid + i * 256;
                int r = v >> 3, c = v & 7;
                int d = r * 32 + ((c ^ (r & 7)) << 2);
                cp16(sA + d, Abase + (size_t)r * K + k0 + c * 4);
                cp16(sB + d, Bbase + (size_t)r * K + k0 + c * 4);
            }
            asm volatile("cp.async.commit_group;\n" ::: "memory");
            asm volatile("cp.async.wait_group 1;\n" ::: "memory");
        } else {
            asm volatile("cp.async.wait_group 0;\n" ::: "memory");
        }
        __syncthreads();

        const float* sA = gsm + (t & 1) * 8192;
        const float* sB = sA + 4096;

#pragma unroll
        for (int ks = 0; ks < 4; ks++) {
            const int kb = ks * 8;
            uint32_t ah[2][4], al[2][4], bh[8][2], bl[8][2];
#pragma unroll
            for (int mi = 0; mi < 2; mi++) {
                int mA = wm0 + mi * 16 + gid;
                split_tf32(sA[sw(mA,     kb + tq)],     ah[mi][0], al[mi][0]);
                split_tf32(sA[sw(mA + 8, kb + tq)],     ah[mi][1], al[mi][1]);
                split_tf32(sA[sw(mA,     kb + tq + 4)], ah[mi][2], al[mi][2]);
                split_tf32(sA[sw(mA + 8, kb + tq + 4)], ah[mi][3], al[mi][3]);
            }
#pragma unroll
            for (int nj = 0; nj < 8; nj++) {
                int nB = wn0 + nj * 8 + gid;
                split_tf32(sB[sw(nB, kb + tq)],     bh[nj][0], bl[nj][0]);
                split_tf32(sB[sw(nB, kb + tq + 4)], bh[nj][1], bl[nj][1]);
            }
#pragma unroll
            for (int mi = 0; mi < 2; mi++)
#pragma unroll
                for (int nj = 0; nj < 8; nj++) {
                    MMA_TF32(acc[mi][nj], al[mi][0], al[mi][1], al[mi][2], al[mi][3],
                             bh[nj][0], bh[nj][1]);
                    MMA_TF32(acc[mi][nj], ah[mi][0], ah[mi][1], ah[mi][2], ah[mi][3],
                             bl[nj][0], bl[nj][1]);
                    MMA_TF32(acc[mi][nj], ah[mi][0], ah[mi][1], ah[mi][2], ah[mi][3],
                             bh[nj][0], bh[nj][1]);
                }
        }
        __syncthreads();
    }

    // ---- epilogue: bias (+res) (+relu), float2 stores ----
#pragma unroll
    for (int nj = 0; nj < 8; nj++) {
        int col = n0 + wn0 + nj * 8 + tq * 2;
        float bx = bias[col], by = bias[col + 1];
#pragma unroll
        for (int mi = 0; mi < 2; mi++) {
            int r0 = m0 + wm0 + mi * 16 + gid;
            int r1 = r0 + 8;
            float v0 = acc[mi][nj][0] + bx, v1 = acc[mi][nj][1] + by;
            float v2 = acc[mi][nj][2] + bx, v3 = acc[mi][nj][3] + by;
            if (res) {
                float2 q0 = *(const float2*)&res[(size_t)r0 * N + col];
                float2 q1 = *(const float2*)&res[(size_t)r1 * N + col];
                v0 += q0.x; v1 += q0.y; v2 += q1.x; v3 += q1.y;
            }
            if (relu) {
                v0 = fmaxf(v0, 0.f); v1 = fmaxf(v1, 0.f);
                v2 = fmaxf(v2, 0.f); v3 = fmaxf(v3, 0.f);
            }
            *(float2*)&C[(size_t)r0 * N + col] = make_float2(v0, v1);
            *(float2*)&C[(size_t)r1 * N + col] = make_float2(v2, v3);
        }
    }
}

// ================= flash-style attention (fp32 SIMT) =========================
#define ATTN_SMEM ((4 * 64 * 65 + 3 * 64) * 4)

__global__ __launch_bounds__(256)
void attn_kernel(const float* __restrict__ Q, const float* __restrict__ K,
                 const float* __restrict__ V, float* __restrict__ O)
{
    extern __shared__ float sm[];
    float* Qs = sm;                 // 64 x 65
    float* Ks = Qs + 64 * 65;
    float* Vs = Ks + 64 * 65;
    float* Ss = Vs + 64 * 65;
    float* mrow = Ss + 64 * 65;     // 64
    float* lrow = mrow + 64;
    float* arow = lrow + 64;

    const int tid = threadIdx.x;
    const int qt = blockIdx.x, h = blockIdx.y, b = blockIdx.z;
    const int q0 = qt * 64;

    for (int idx = tid; idx < 4096; idx += 256) {
        int q = idx >> 6, d = idx & 63;
        Qs[q * 65 + d] = Q[((b * SEQ + q0 + q) * HEADS + h) * DH + d] * 0.125f;
    }
    if (tid < 64) { mrow[tid] = -1e30f; lrow[tid] = 0.f; }

    const int ty = tid >> 4, tx = tid & 15;
    float o[4][4] = {};

    for (int kt = 0; kt < SEQ / 64; kt++) {
        __syncthreads();
        int k0 = kt * 64;
        for (int idx = tid; idx < 4096; idx += 256) {
            int r = idx >> 6, d = idx & 63;
            int g = ((b * SEQ + k0 + r) * HEADS + h) * DH + d;
            Ks[r * 65 + d] = K[g];
            Vs[r * 65 + d] = V[g];
        }
        __syncthreads();

        float s[4][4] = {};
#pragma unroll
        for (int d = 0; d < 64; d++) {
            float a[4], bb[4];
#pragma unroll
            for (int i = 0; i < 4; i++) a[i]  = Qs[(ty * 4 + i) * 65 + d];
#pragma unroll
            for (int j = 0; j < 4; j++) bb[j] = Ks[(tx * 4 + j) * 65 + d];
#pragma unroll
            for (int i = 0; i < 4; i++)
#pragma unroll
                for (int j = 0; j < 4; j++)
                    s[i][j] = fmaf(a[i], bb[j], s[i][j]);
        }
#pragma unroll
        for (int i = 0; i < 4; i++)
#pragma unroll
            for (int j = 0; j < 4; j++)
                Ss[(ty * 4 + i) * 65 + tx * 4 + j] = s[i][j];
        __syncthreads();

        if (tid < 64) {
            float mold = mrow[tid];
            float mx = mold;
#pragma unroll 8
            for (int kk = 0; kk < 64; kk++) mx = fmaxf(mx, Ss[tid * 65 + kk]);
            float alpha = __expf(mold - mx);
            float l = lrow[tid] * alpha;
#pragma unroll 8
            for (int kk = 0; kk < 64; kk++) {
                float p = __expf(Ss[tid * 65 + kk] - mx);
                Ss[tid * 65 + kk] = p;
                l += p;
            }
            mrow[tid] = mx; lrow[tid] = l; arow[tid] = alpha;
        }
        __syncthreads();

#pragma unroll
        for (int i = 0; i < 4; i++) {
            float al = arow[ty * 4 + i];
#pragma unroll
            for (int j = 0; j < 4; j++) o[i][j] *= al;
        }
#pragma unroll
        for (int kk = 0; kk < 64; kk++) {
            float a[4], bb[4];
#pragma unroll
            for (int i = 0; i < 4; i++) a[i]  = Ss[(ty * 4 + i) * 65 + kk];
#pragma unroll
            for (int j = 0; j < 4; j++) bb[j] = Vs[kk * 65 + tx * 4 + j];
#pragma unroll
            for (int i = 0; i < 4; i++)
#pragma unroll
                for (int j = 0; j < 4; j++)
                    o[i][j] = fmaf(a[i], bb[j], o[i][j]);
        }
    }

#pragma unroll
    for (int i = 0; i < 4; i++) {
        float inv = 1.f / lrow[ty * 4 + i];
#pragma unroll
        for (int j = 0; j < 4; j++)
            O[((b * SEQ + q0 + ty * 4 + i) * HEADS + h) * DH + tx * 4 + j] = o[i][j] * inv;
    }
}

// ================= LayerNorm (one block per row of 512) ======================
__global__ __launch_bounds__(128)
void ln_kernel(const float* __restrict__ in, const float* __restrict__ gam,
               const float* __restrict__ bet, float* __restrict__ out)
{
    const int row = blockIdx.x;
    const int tid = threadIdx.x;
    const float* p = in + row * HID;

    float4 v = *(const float4*)&p[tid * 4];
    float s  = v.x + v.y + v.z + v.w;
    float ss = v.x * v.x + v.y * v.y + v.z * v.z + v.w * v.w;
#pragma unroll
    for (int off = 16; off; off >>= 1) {
        s  += __shfl_down_sync(0xffffffffu, s,  off);
        ss += __shfl_down_sync(0xffffffffu, ss, off);
    }
    __shared__ float sh_s[4], sh_ss[4];
    if ((tid & 31) == 0) { sh_s[tid >> 5] = s; sh_ss[tid >> 5] = ss; }
    __syncthreads();
    float tot  = sh_s[0]  + sh_s[1]  + sh_s[2]  + sh_s[3];
    float tot2 = sh_ss[0] + sh_ss[1] + sh_ss[2] + sh_ss[3];
    float mean = tot * (1.f / HID);
    float var  = tot2 * (1.f / HID) - mean * mean;
    float rstd = rsqrtf(var + 1e-5f);

    float4 gg = *(const float4*)&gam[tid * 4];
    float4 bb = *(const float4*)&bet[tid * 4];
    float4 r;
    r.x = (v.x - mean) * rstd * gg.x + bb.x;
    r.y = (v.y - mean) * rstd * gg.y + bb.y;
    r.z = (v.z - mean) * rstd * gg.z + bb.z;
    r.w = (v.w - mean) * rstd * gg.w + bb.w;
    *(float4*)&out[row * HID + tid * 4] = r;
}

// ================= norm-softmax pooling (one block per batch) ================
__global__ __launch_bounds__(512)
void pool_kernel(const float* __restrict__ x, float* __restrict__ pooled)
{
    __shared__ float sn[SEQ];
    __shared__ float red[512];
    const int b = blockIdx.x, tid = threadIdx.x;
    const float* xb = x + b * SEQ * HID;

    for (int t = tid; t < SEQ; t += 512) {
        const float* r = xb + t * HID;
        float ss = 0.f;
        for (int d = 0; d < HID; d += 4) {
            float4 v = *(const float4*)&r[d];
            ss += v.x * v.x + v.y * v.y + v.z * v.z + v.w * v.w;
        }
        sn[t] = sqrtf(ss);
    }
    __syncthreads();

    red[tid] = fmaxf(sn[tid], sn[tid + 512]);
    __syncthreads();
    for (int off = 256; off; off >>= 1) {
        if (tid < off) red[tid] = fmaxf(red[tid], red[tid + off]);
        __syncthreads();
    }
    float mx = red[0];
    __syncthreads();

    float e0 = __expf(sn[tid] - mx);
    float e1 = __expf(sn[tid + 512] - mx);
    sn[tid] = e0; sn[tid + 512] = e1;
    red[tid] = e0 + e1;
    __syncthreads();
    for (int off = 256; off; off >>= 1) {
        if (tid < off) red[tid] += red[tid + off];
        __syncthreads();
    }
    float inv = 1.f / red[0];

    float acc = 0.f;
    for (int t = 0; t < SEQ; t++)
        acc = fmaf(sn[t], xb[t * HID + tid], acc);
    pooled[b * HID + tid] = acc * inv;
}

// ================= classifier head (one block per batch) =====================
__global__ __launch_bounds__(256)
void cls_kernel(const float* __restrict__ pooled,
                const float* __restrict__ w1, const float* __restrict__ b1,
                const float* __restrict__ w2, const float* __restrict__ b2,
                float* __restrict__ out)
{
    __shared__ float ps[HID];
    __shared__ float hs[256];
    const int b = blockIdx.x, tid = threadIdx.x;
    ps[tid]       = pooled[b * HID + tid];
    ps[tid + 256] = pooled[b * HID + tid + 256];
    __syncthreads();

    float acc = b1[tid];
    const float* wr = w1 + tid * HID;
    for (int k2 = 0; k2 < HID; k2 += 4) {
        float4 w = *(const float4*)&wr[k2];
        acc += w.x * ps[k2] + w.y * ps[k2 + 1] + w.z * ps[k2 + 2] + w.w * ps[k2 + 3];
    }
    hs[tid] = fmaxf(acc, 0.f);
    __syncthreads();

    if (tid < 2) {
        float a = b2[tid];
        const float* w = w2 + tid * 256;
        for (int j = 0; j < 256; j++) a = fmaf(hs[j], w[j], a);
        out[b * 2 + tid] = a;
    }
}

// ================= launch ====================================================
extern "C" void kernel_launch(void* const* d_in, const int* in_sizes, int n_in,
                              void* d_out, int out_size)
{
    const float* trg   = (const float*)d_in[0];
    const float* src   = (const float*)d_in[1];
    const float* ln_g  = (const float*)d_in[2];
    const float* ln_b  = (const float*)d_in[3];
    const float* wq    = (const float*)d_in[4];
    const float* bq    = (const float*)d_in[5];
    const float* wk    = (const float*)d_in[6];
    const float* bk    = (const float*)d_in[7];
    const float* wv    = (const float*)d_in[8];
    const float* bv    = (const float*)d_in[9];
    const float* wo    = (const float*)d_in[10];
    const float* bo    = (const float*)d_in[11];
    const float* pf1_w = (const float*)d_in[12];
    const float* pf1_b = (const float*)d_in[13];
    const float* pf2_w = (const float*)d_in[14];
    const float* pf2_b = (const float*)d_in[15];
    const float* fc1_w = (const float*)d_in[16];
    const float* fc1_b = (const float*)d_in[17];
    const float* fc2_w = (const float*)d_in[18];
    const float* fc2_b = (const float*)d_in[19];
    float* out = (float*)d_out;

    float *q, *k, *v, *ctx, *xs, *xn, *x2, *hb, *pool;
    cudaGetSymbolAddress((void**)&q,    g_q);
    cudaGetSymbolAddress((void**)&k,    g_k);
    cudaGetSymbolAddress((void**)&v,    g_v);
    cudaGetSymbolAddress((void**)&ctx,  g_ctx);
    cudaGetSymbolAddress((void**)&xs,   g_xs);
    cudaGetSymbolAddress((void**)&xn,   g_xn);
    cudaGetSymbolAddress((void**)&x2,   g_x2);
    cudaGetSymbolAddress((void**)&hb,   g_h);
    cudaGetSymbolAddress((void**)&pool, g_pool);

    cudaFuncSetAttribute(attn_kernel,
                         cudaFuncAttributeMaxDynamicSharedMemorySize, ATTN_SMEM);
    cudaFuncSetAttribute(gemm_tf32x3_kernel,
                         cudaFuncAttributeMaxDynamicSharedMemorySize, 65536);

    const int M = MTOT;
    dim3 thr(256);
    dim3 g512(HID / 128, M / 128);   // (4, 128)
    dim3 gpf (PF  / 128, M / 128);   // (16, 128)

    // projections
    gemm_tf32x3_kernel<<<g512, thr, 65536>>>(trg, wq, bq, nullptr, q, M, HID, HID, 0);
    gemm_tf32x3_kernel<<<g512, thr, 65536>>>(src, wk, bk, nullptr, k, M, HID, HID, 0);
    gemm_tf32x3_kernel<<<g512, thr, 65536>>>(src, wv, bv, nullptr, v, M, HID, HID, 0);

    // attention
    attn_kernel<<<dim3(SEQ / 64, HEADS, BATCH), 256, ATTN_SMEM>>>(q, k, v, ctx);

    // O-projection + residual, LN
    gemm_tf32x3_kernel<<<g512, thr, 65536>>>(ctx, wo, bo, trg, xs, M, HID, HID, 0);
    ln_kernel<<<M, 128>>>(xs, ln_g, ln_b, xn);

    // FFN + residual, LN
    gemm_tf32x3_kernel<<<gpf,  thr, 65536>>>(xn, pf1_w, pf1_b, nullptr, hb, M, PF, HID, 1);
    gemm_tf32x3_kernel<<<g512, thr, 65536>>>(hb, pf2_w, pf2_b, xn, xs, M, HID, PF, 0);
    ln_kernel<<<M, 128>>>(xs, ln_g, ln_b, x2);

    // pooling + classifier
    pool_kernel<<<BATCH, 512>>>(x2, pool);
    cls_kernel<<<BATCH, 256>>>(pool, fc1_w, fc1_b, fc2_w, fc2_b, out);
}